// round 6
// baseline (speedup 1.0000x reference)
#include <cuda_runtime.h>
#include <cstdint>
#include <cstddef>

#define NNODE 50000
#define NEDGE 800000
#define DD 128     // node feature dim
#define DE 64      // edge feature dim
#define HH 256     // hidden dim (2*D)
#define BN_EPS 1e-5f

// ---------------- device scratch (static; no allocations allowed) ----------------
__device__ float g_hpre[(size_t)NNODE * DD];
__device__ float g_y1[(size_t)NNODE * HH];
__device__ float g_W1T[DD * HH];
__device__ float g_W2T[HH * DD];
__device__ int   g_src[NEDGE];
__device__ int   g_dst[NEDGE];
__device__ float g_sum1[HH], g_sq1[HH], g_sum2[DD], g_sq2[DD];
__device__ float g_scale1[HH], g_shift1[HH], g_scale2[DD], g_shift2[DD];

__device__ __forceinline__ void red_add_v4(float* a, float x, float y, float z, float w) {
    asm volatile("red.global.add.v4.f32 [%0], {%1,%2,%3,%4};"
                 :: "l"(a), "f"(x), "f"(y), "f"(z), "f"(w) : "memory");
}

// packed fp32x2 helpers (sm_100+)
__device__ __forceinline__ unsigned long long bcast2(float a) {
    unsigned long long r;
    unsigned int u = __float_as_uint(a);
    asm("mov.b64 %0, {%1, %1};" : "=l"(r) : "r"(u));
    return r;
}
__device__ __forceinline__ void ffma2(unsigned long long& d, unsigned long long a,
                                      unsigned long long b) {
    asm("fma.rn.f32x2 %0, %1, %2, %0;" : "+l"(d) : "l"(a), "l"(b));
}
__device__ __forceinline__ float2 up2(unsigned long long v) {
    float2 f;
    f.x = __uint_as_float((unsigned int)v);
    f.y = __uint_as_float((unsigned int)(v >> 32));
    return f;
}

// tf32 helpers (baseline PTX, works on sm_103 non-'a' target)
__device__ __forceinline__ uint32_t f2tf(float f) {
    uint32_t u;
    asm("cvt.rna.tf32.f32 %0, %1;" : "=r"(u) : "f"(f));
    return u;
}
__device__ __forceinline__ void mma_tf32(float* d, const uint32_t* a, const uint32_t* b) {
    asm volatile(
        "mma.sync.aligned.m16n8k8.row.col.f32.tf32.tf32.f32 "
        "{%0,%1,%2,%3}, {%4,%5,%6,%7}, {%8,%9}, {%0,%1,%2,%3};"
        : "+f"(d[0]), "+f"(d[1]), "+f"(d[2]), "+f"(d[3])
        : "r"(a[0]), "r"(a[1]), "r"(a[2]), "r"(a[3]), "r"(b[0]), "r"(b[1]));
}

// ---------------- 1) decode edge_index (int64 or int32, detected on device) -----
__global__ void k_decode(const int* __restrict__ ei) {
    bool is64 = ((ei[1] | ei[3] | ei[5] | ei[7] | ei[9] | ei[11] | ei[13] | ei[15]) == 0);
    int stride = gridDim.x * blockDim.x;
    for (int i = blockIdx.x * blockDim.x + threadIdx.x; i < NEDGE; i += stride) {
        int s, d;
        if (is64) {
            const long long* p = (const long long*)ei;
            s = (int)p[i];
            d = (int)p[NEDGE + i];
        } else {
            s = ei[i];
            d = ei[NEDGE + i];
        }
        g_src[i] = s;
        g_dst[i] = d;
    }
}

// ---------------- 2) transposes + zero stats ------------------------------------
__global__ void k_misc(const float* __restrict__ W1, const float* __restrict__ W2) {
    int stride = gridDim.x * blockDim.x;
    int t0 = blockIdx.x * blockDim.x + threadIdx.x;
    for (int i = t0; i < DD * HH; i += stride) { int k = i / HH, j = i % HH; g_W1T[i] = W1[j * DD + k]; }
    for (int i = t0; i < HH * DD; i += stride) { int k = i / DD, j = i % DD; g_W2T[i] = W2[j * HH + k]; }
    for (int i = t0; i < HH; i += stride) { g_sum1[i] = 0.f; g_sq1[i] = 0.f; }
    for (int i = t0; i < DD; i += stride) { g_sum2[i] = 0.f; g_sq2[i] = 0.f; }
}

// ---------------- 3) hpre = (1+eps) * x -----------------------------------------
__global__ void k_hpre(const float* __restrict__ x, const float* __restrict__ epsp) {
    float c = 1.0f + *epsp;
    int stride = gridDim.x * blockDim.x;
    const float4* x4 = (const float4*)x;
    float4* h4 = (float4*)g_hpre;
    for (int i = blockIdx.x * blockDim.x + threadIdx.x; i < NNODE * DD / 4; i += stride) {
        float4 v = x4[i];
        v.x *= c; v.y *= c; v.z *= c; v.w *= c;
        h4[i] = v;
    }
}

// ---------------- 4) edge kernel: tf32 mma.sync GEMM + gather + relu + scatter ---
// Per CTA: 128 edges x 128 out, K=64. Warp w: rows [w*16, w*16+16), all 128 cols.
#define EPAD 68
#define DPAD 132
#define SM_IDX_OFF (2 * 128 * EPAD)                 // in floats
#define SM_EDGE_TOTAL (SM_IDX_OFF * 4 + 256 * 4)    // bytes

__global__ __launch_bounds__(256) void k_edge(const float* __restrict__ ea,
                                              const float* __restrict__ x,
                                              const float* __restrict__ be,
                                              const float* __restrict__ We) {
    extern __shared__ float sm[];
    float* sA = sm;                        // [128][68] tf32 bits (as float storage)
    float* sB = sm + 128 * EPAD;           // [128][68] tf32 bits
    float* sD = sm;                        // [128][132] fp32, overlaps tiles
    int* sSrc = (int*)(sm + SM_IDX_OFF);
    int* sDst = sSrc + 128;

    int tid = threadIdx.x;
    int wid = tid >> 5;
    int lane = tid & 31;
    int gid = lane >> 2, tig = lane & 3;
    int e0 = blockIdx.x * 128;

    // tile fill with on-the-fly tf32 conversion (cvt.rna)
#pragma unroll
    for (int r = 0; r < 8; r++) {
        int i = tid + 256 * r;             // 0..2047
        int row = i >> 4, c4 = i & 15;
        float4 va = *(const float4*)(ea + (size_t)(e0 + row) * DE + c4 * 4);
        uint4 ua = make_uint4(f2tf(va.x), f2tf(va.y), f2tf(va.z), f2tf(va.w));
        *(uint4*)&sA[row * EPAD + c4 * 4] = ua;
        float4 vb = *(const float4*)(We + (size_t)row * DE + c4 * 4);
        uint4 ub = make_uint4(f2tf(vb.x), f2tf(vb.y), f2tf(vb.z), f2tf(vb.w));
        *(uint4*)&sB[row * EPAD + c4 * 4] = ub;
    }
    if (tid < 128) { sSrc[tid] = g_src[e0 + tid]; sDst[tid] = g_dst[e0 + tid]; }
    __syncthreads();

    float acc[16][4];
#pragma unroll
    for (int nt = 0; nt < 16; nt++)
#pragma unroll
        for (int j = 0; j < 4; j++) acc[nt][j] = 0.f;

    const uint32_t* uA = (const uint32_t*)sA;
    const uint32_t* uB = (const uint32_t*)sB;
    int arow = wid * 16 + gid;
#pragma unroll
    for (int ks = 0; ks < 8; ks++) {
        int k0 = ks * 8;
        uint32_t a[4];
        a[0] = uA[arow * EPAD + k0 + tig];
        a[1] = uA[(arow + 8) * EPAD + k0 + tig];
        a[2] = uA[arow * EPAD + k0 + 4 + tig];
        a[3] = uA[(arow + 8) * EPAD + k0 + 4 + tig];
#pragma unroll
        for (int nt = 0; nt < 16; nt++) {
            uint32_t b[2];
            b[0] = uB[(nt * 8 + gid) * EPAD + k0 + tig];
            b[1] = uB[(nt * 8 + gid) * EPAD + k0 + 4 + tig];
            mma_tf32(acc[nt], a, b);
        }
    }
    __syncthreads();   // all warps done reading tiles; sD may now overwrite them

    // stage accumulators to smem in natural [edge][col] layout
#pragma unroll
    for (int nt = 0; nt < 16; nt++) {
        int col = nt * 8 + 2 * tig;
        int row = wid * 16 + gid;
        *(float2*)&sD[row * DPAD + col] = make_float2(acc[nt][0], acc[nt][1]);
        *(float2*)&sD[(row + 8) * DPAD + col] = make_float2(acc[nt][2], acc[nt][3]);
    }
    __syncthreads();

    // epilogue: warp w -> edges (w&3)*32+lane, column half (w>>2)*64
    int erow = (wid & 3) * 32 + lane;
    int c0 = (wid >> 2) * 64;
    int s = sSrc[erow];
    int d = sDst[erow];
    const float4* xr = (const float4*)(x + (size_t)s * DD + c0);
    const float4* ber = (const float4*)(be + c0);
    const float* drow = &sD[erow * DPAD + c0];
    float* dptr = g_hpre + (size_t)d * DD + c0;
#pragma unroll
    for (int c4 = 0; c4 < 16; c4++) {
        float4 dv = *(const float4*)&drow[c4 * 4];
        float4 xv = xr[c4];
        float4 bv = ber[c4];
        float m0 = fmaxf(dv.x + xv.x + bv.x, 0.f);
        float m1 = fmaxf(dv.y + xv.y + bv.y, 0.f);
        float m2 = fmaxf(dv.z + xv.z + bv.z, 0.f);
        float m3 = fmaxf(dv.w + xv.w + bv.w, 0.f);
        red_add_v4(dptr + c4 * 4, m0, m1, m2, m3);
    }
}

// ---------------- 5) GEMM1: y1 = hpre @ W1^T + b1, accumulate BN stats ----------
__global__ __launch_bounds__(256) void k_gemm1(const float* __restrict__ bias) {
    __shared__ float As[128 * 36];
    __shared__ float Bs[32 * 128];
    __shared__ float sSum[128];
    __shared__ float sSq[128];
    int tid = threadIdx.x;
    int m0 = blockIdx.x * 128;
    int n0 = blockIdx.y * 128;
    int tx8 = (tid & 15) * 8;
    int ty8 = (tid >> 4) * 8;
    unsigned long long acc[8][4];
#pragma unroll
    for (int i = 0; i < 8; i++)
#pragma unroll
        for (int j = 0; j < 4; j++) acc[i][j] = 0ull;

    for (int kc = 0; kc < DD; kc += 32) {
#pragma unroll
        for (int r = 0; r < 4; r++) {
            int idx = tid + 256 * r;
            int row = idx >> 3, c4 = idx & 7;
            int m = m0 + row;
            float4 v = make_float4(0.f, 0.f, 0.f, 0.f);
            if (m < NNODE) v = *(const float4*)&g_hpre[(size_t)m * DD + kc + c4 * 4];
            *(float4*)&As[row * 36 + c4 * 4] = v;
        }
#pragma unroll
        for (int r = 0; r < 4; r++) {
            int idx = tid + 256 * r;
            int k = idx >> 5, c4 = idx & 31;
            *(float4*)&Bs[k * 128 + c4 * 4] = *(const float4*)&g_W1T[(size_t)(kc + k) * HH + n0 + c4 * 4];
        }
        __syncthreads();
#pragma unroll
        for (int k = 0; k < 32; k += 4) {
            float4 a4[8];
#pragma unroll
            for (int i = 0; i < 8; i++) a4[i] = *(const float4*)&As[(ty8 + i) * 36 + k];
#pragma unroll
            for (int kk = 0; kk < 4; kk++) {
                const unsigned long long* bp = (const unsigned long long*)&Bs[(k + kk) * 128 + tx8];
                unsigned long long b0 = bp[0], b1 = bp[1], b2 = bp[2], b3 = bp[3];
#pragma unroll
                for (int i = 0; i < 8; i++) {
                    unsigned long long a2 = bcast2(((const float*)&a4[i])[kk]);
                    ffma2(acc[i][0], a2, b0);
                    ffma2(acc[i][1], a2, b1);
                    ffma2(acc[i][2], a2, b2);
                    ffma2(acc[i][3], a2, b3);
                }
            }
        }
        __syncthreads();
    }

    float4 bb0 = *(const float4*)&bias[n0 + tx8];
    float4 bb1 = *(const float4*)&bias[n0 + tx8 + 4];
    float bv[8] = {bb0.x, bb0.y, bb0.z, bb0.w, bb1.x, bb1.y, bb1.z, bb1.w};
    float lsum[8], lsq[8];
#pragma unroll
    for (int j = 0; j < 8; j++) { lsum[j] = 0.f; lsq[j] = 0.f; }
#pragma unroll
    for (int i = 0; i < 8; i++) {
        int m = m0 + ty8 + i;
        if (m < NNODE) {
            float2 pr[4] = {up2(acc[i][0]), up2(acc[i][1]), up2(acc[i][2]), up2(acc[i][3])};
            float v[8];
#pragma unroll
            for (int j = 0; j < 8; j++) {
                float a = (j & 1) ? pr[j >> 1].y : pr[j >> 1].x;
                v[j] = a + bv[j];
                lsum[j] += v[j];
                lsq[j] += v[j] * v[j];
            }
            float4* o = (float4*)&g_y1[(size_t)m * HH + n0 + tx8];
            o[0] = make_float4(v[0], v[1], v[2], v[3]);
            o[1] = make_float4(v[4], v[5], v[6], v[7]);
        }
    }
    if (tid < 128) { sSum[tid] = 0.f; sSq[tid] = 0.f; }
    __syncthreads();
#pragma unroll
    for (int j = 0; j < 8; j++) {
        atomicAdd(&sSum[tx8 + j], lsum[j]);
        atomicAdd(&sSq[tx8 + j], lsq[j]);
    }
    __syncthreads();
    if (tid < 128) {
        atomicAdd(&g_sum1[n0 + tid], sSum[tid]);
        atomicAdd(&g_sq1[n0 + tid], sSq[tid]);
    }
}

// ---------------- 6) fold BN1 stats into scale/shift ----------------------------
__global__ void k_stat1(const float* __restrict__ g, const float* __restrict__ beta) {
    int j = threadIdx.x;
    if (j < HH) {
        float mu = g_sum1[j] / (float)NNODE;
        float var = g_sq1[j] / (float)NNODE - mu * mu;
        float sc = g[j] * rsqrtf(var + BN_EPS);
        g_scale1[j] = sc;
        g_shift1[j] = beta[j] - mu * sc;
    }
}

// ---------------- 7) GEMM2: out = relu(bn1(y1)) @ W2^T + b2, accumulate stats ---
__global__ __launch_bounds__(256) void k_gemm2(const float* __restrict__ bias,
                                               float* __restrict__ out) {
    __shared__ float As[128 * 36];
    __shared__ float Bs[32 * 128];
    __shared__ float sSum[128];
    __shared__ float sSq[128];
    int tid = threadIdx.x;
    int m0 = blockIdx.x * 128;
    int tx8 = (tid & 15) * 8;
    int ty8 = (tid >> 4) * 8;
    unsigned long long acc[8][4];
#pragma unroll
    for (int i = 0; i < 8; i++)
#pragma unroll
        for (int j = 0; j < 4; j++) acc[i][j] = 0ull;

    for (int kc = 0; kc < HH; kc += 32) {
#pragma unroll
        for (int r = 0; r < 4; r++) {
            int idx = tid + 256 * r;
            int row = idx >> 3, c4 = idx & 7;
            int m = m0 + row;
            int col = kc + c4 * 4;
            float4 v = make_float4(0.f, 0.f, 0.f, 0.f);
            if (m < NNODE) v = *(const float4*)&g_y1[(size_t)m * HH + col];
            float4 sc = *(const float4*)&g_scale1[col];
            float4 sh = *(const float4*)&g_shift1[col];
            v.x = fmaxf(fmaf(v.x, sc.x, sh.x), 0.f);
            v.y = fmaxf(fmaf(v.y, sc.y, sh.y), 0.f);
            v.z = fmaxf(fmaf(v.z, sc.z, sh.z), 0.f);
            v.w = fmaxf(fmaf(v.w, sc.w, sh.w), 0.f);
            *(float4*)&As[row * 36 + c4 * 4] = v;
        }
#pragma unroll
        for (int r = 0; r < 4; r++) {
            int idx = tid + 256 * r;
            int k = idx >> 5, c4 = idx & 31;
            *(float4*)&Bs[k * 128 + c4 * 4] = *(const float4*)&g_W2T[(size_t)(kc + k) * DD + c4 * 4];
        }
        __syncthreads();
#pragma unroll
        for (int k = 0; k < 32; k += 4) {
            float4 a4[8];
#pragma unroll
            for (int i = 0; i < 8; i++) a4[i] = *(const float4*)&As[(ty8 + i) * 36 + k];
#pragma unroll
            for (int kk = 0; kk < 4; kk++) {
                const unsigned long long* bp = (const unsigned long long*)&Bs[(k + kk) * 128 + tx8];
                unsigned long long b0 = bp[0], b1 = bp[1], b2 = bp[2], b3 = bp[3];
#pragma unroll
                for (int i = 0; i < 8; i++) {
                    unsigned long long a2 = bcast2(((const float*)&a4[i])[kk]);
                    ffma2(acc[i][0], a2, b0);
                    ffma2(acc[i][1], a2, b1);
                    ffma2(acc[i][2], a2, b2);
                    ffma2(acc[i][3], a2, b3);
                }
            }
        }
        __syncthreads();
    }

    float4 bb0 = *(const float4*)&bias[tx8];
    float4 bb1 = *(const float4*)&bias[tx8 + 4];
    float bv[8] = {bb0.x, bb0.y, bb0.z, bb0.w, bb1.x, bb1.y, bb1.z, bb1.w};
    float lsum[8], lsq[8];
#pragma unroll
    for (int j = 0; j < 8; j++) { lsum[j] = 0.f; lsq[j] = 0.f; }
#pragma unroll
    for (int i = 0; i < 8; i++) {
        int m = m0 + ty8 + i;
        if (m < NNODE) {
            float2 pr[4] = {up2(acc[i][0]), up2(acc[i][1]), up2(acc[i][2]), up2(acc[i][3])};
            float v[8];
#pragma unroll
            for (int j = 0; j < 8; j++) {
                float a = (j & 1) ? pr[j >> 1].y : pr[j >> 1].x;
                v[j] = a + bv[j];
                lsum[j] += v[j];
                lsq[j] += v[j] * v[j];
            }
            float4* o = (float4*)&out[(size_t)m * DD + tx8];
            o[0] = make_float4(v[0], v[1], v[2], v[3]);
            o[1] = make_float4(v[4], v[5], v[6], v[7]);
        }
    }
    if (tid < 128) { sSum[tid] = 0.f; sSq[tid] = 0.f; }
    __syncthreads();
#pragma unroll
    for (int j = 0; j < 8; j++) {
        atomicAdd(&sSum[tx8 + j], lsum[j]);
        atomicAdd(&sSq[tx8 + j], lsq[j]);
    }
    __syncthreads();
    if (tid < 128) {
        atomicAdd(&g_sum2[tid], sSum[tid]);
        atomicAdd(&g_sq2[tid], sSq[tid]);
    }
}

// ---------------- 8) fold BN2 stats --------------------------------------------
__global__ void k_stat2(const float* __restrict__ g, const float* __restrict__ beta) {
    int j = threadIdx.x;
    if (j < DD) {
        float mu = g_sum2[j] / (float)NNODE;
        float var = g_sq2[j] / (float)NNODE - mu * mu;
        float sc = g[j] * rsqrtf(var + BN_EPS);
        g_scale2[j] = sc;
        g_shift2[j] = beta[j] - mu * sc;
    }
}

// ---------------- 9) final elementwise: out = relu(bn2(out)) --------------------
__global__ void k_final(float* __restrict__ out) {
    int stride = gridDim.x * blockDim.x;
    float4* o4 = (float4*)out;
    for (int i = blockIdx.x * blockDim.x + threadIdx.x; i < NNODE * DD / 4; i += stride) {
        int col = (i & 31) * 4;
        float4 sc = *(const float4*)&g_scale2[col];
        float4 sh = *(const float4*)&g_shift2[col];
        float4 v = o4[i];
        v.x = fmaxf(fmaf(v.x, sc.x, sh.x), 0.f);
        v.y = fmaxf(fmaf(v.y, sc.y, sh.y), 0.f);
        v.z = fmaxf(fmaf(v.z, sc.z, sh.z), 0.f);
        v.w = fmaxf(fmaf(v.w, sc.w, sh.w), 0.f);
        o4[i] = v;
    }
}

// ---------------- launcher ------------------------------------------------------
extern "C" void kernel_launch(void* const* d_in, const int* in_sizes, int n_in,
                              void* d_out, int out_size) {
    const float* x   = (const float*)d_in[0];
    const int*   ei  = (const int*)d_in[1];
    const float* ea  = (const float*)d_in[2];
    const float* We  = (const float*)d_in[3];
    const float* be  = (const float*)d_in[4];
    const float* W1  = (const float*)d_in[5];
    const float* b1  = (const float*)d_in[6];
    const float* g1  = (const float*)d_in[7];
    const float* be1 = (const float*)d_in[8];
    const float* W2  = (const float*)d_in[9];
    const float* b2  = (const float*)d_in[10];
    const float* g2  = (const float*)d_in[11];
    const float* be2 = (const float*)d_in[12];
    const float* eps = (const float*)d_in[13];
    float* out = (float*)d_out;

    cudaFuncSetAttribute(k_edge, cudaFuncAttributeMaxDynamicSharedMemorySize, SM_EDGE_TOTAL);

    k_decode<<<1024, 256>>>(ei);
    k_misc<<<64, 256>>>(W1, W2);
    k_hpre<<<2048, 256>>>(x, eps);
    k_edge<<<NEDGE / 128, 256, SM_EDGE_TOTAL>>>(ea, x, be, We);
    dim3 g1grid((NNODE + 127) / 128, 2);
    k_gemm1<<<g1grid, 256>>>(b1);
    k_stat1<<<1, 256>>>(g1, be1);
    k_gemm2<<<(NNODE + 127) / 128, 256>>>(b2, out);
    k_stat2<<<1, 128>>>(g2, be2);
    k_final<<<2048, 256>>>(out);
}

// round 10
// speedup vs baseline: 1.0625x; 1.0625x over previous
#include <cuda_runtime.h>
#include <cstdint>
#include <cstddef>

#define NNODE 50000
#define NEDGE 800000
#define DD 128     // node feature dim
#define DE 64      // edge feature dim
#define HH 256     // hidden dim (2*D)
#define BN_EPS 1e-5f

// ---------------- device scratch (static; no allocations allowed) ----------------
__device__ float g_hpre[(size_t)NNODE * DD];
__device__ float g_y1[(size_t)NNODE * HH];
__device__ float g_W1T[DD * HH];
__device__ float g_W2T[HH * DD];
__device__ int   g_src[NEDGE];
__device__ int   g_dst[NEDGE];
__device__ float g_sum1[HH], g_sq1[HH], g_sum2[DD], g_sq2[DD];
__device__ float g_scale1[HH], g_shift1[HH], g_scale2[DD], g_shift2[DD];

__device__ __forceinline__ void red_add_v4(float* a, float x, float y, float z, float w) {
    asm volatile("red.global.add.v4.f32 [%0], {%1,%2,%3,%4};"
                 :: "l"(a), "f"(x), "f"(y), "f"(z), "f"(w) : "memory");
}

// packed fp32x2 helpers (sm_100+)
__device__ __forceinline__ unsigned long long bcast2(float a) {
    unsigned long long r;
    unsigned int u = __float_as_uint(a);
    asm("mov.b64 %0, {%1, %1};" : "=l"(r) : "r"(u));
    return r;
}
__device__ __forceinline__ void ffma2(unsigned long long& d, unsigned long long a,
                                      unsigned long long b) {
    asm("fma.rn.f32x2 %0, %1, %2, %0;" : "+l"(d) : "l"(a), "l"(b));
}
__device__ __forceinline__ float2 up2(unsigned long long v) {
    float2 f;
    f.x = __uint_as_float((unsigned int)v);
    f.y = __uint_as_float((unsigned int)(v >> 32));
    return f;
}

// tf32 helpers (baseline PTX, works on sm_103 non-'a' target)
__device__ __forceinline__ uint32_t f2tf(float f) {
    uint32_t u;
    asm("cvt.rna.tf32.f32 %0, %1;" : "=r"(u) : "f"(f));
    return u;
}
__device__ __forceinline__ void mma_tf32(float* d, const uint32_t* a, uint32_t b0, uint32_t b1) {
    asm volatile(
        "mma.sync.aligned.m16n8k8.row.col.f32.tf32.tf32.f32 "
        "{%0,%1,%2,%3}, {%4,%5,%6,%7}, {%8,%9}, {%0,%1,%2,%3};"
        : "+f"(d[0]), "+f"(d[1]), "+f"(d[2]), "+f"(d[3])
        : "r"(a[0]), "r"(a[1]), "r"(a[2]), "r"(a[3]), "r"(b0), "r"(b1));
}

// ---------------- 1) decode edge_index (int64 or int32, detected on device) -----
__global__ void k_decode(const int* __restrict__ ei) {
    bool is64 = ((ei[1] | ei[3] | ei[5] | ei[7] | ei[9] | ei[11] | ei[13] | ei[15]) == 0);
    int stride = gridDim.x * blockDim.x;
    for (int i = blockIdx.x * blockDim.x + threadIdx.x; i < NEDGE; i += stride) {
        int s, d;
        if (is64) {
            const long long* p = (const long long*)ei;
            s = (int)p[i];
            d = (int)p[NEDGE + i];
        } else {
            s = ei[i];
            d = ei[NEDGE + i];
        }
        g_src[i] = s;
        g_dst[i] = d;
    }
}

// ---------------- 2) transposes + zero stats ------------------------------------
__global__ void k_misc(const float* __restrict__ W1, const float* __restrict__ W2) {
    int stride = gridDim.x * blockDim.x;
    int t0 = blockIdx.x * blockDim.x + threadIdx.x;
    for (int i = t0; i < DD * HH; i += stride) { int k = i / HH, j = i % HH; g_W1T[i] = W1[j * DD + k]; }
    for (int i = t0; i < HH * DD; i += stride) { int k = i / DD, j = i % DD; g_W2T[i] = W2[j * HH + k]; }
    for (int i = t0; i < HH; i += stride) { g_sum1[i] = 0.f; g_sq1[i] = 0.f; }
    for (int i = t0; i < DD; i += stride) { g_sum2[i] = 0.f; g_sq2[i] = 0.f; }
}

// ---------------- 3) hpre = (1+eps) * x -----------------------------------------
__global__ void k_hpre(const float* __restrict__ x, const float* __restrict__ epsp) {
    float c = 1.0f + *epsp;
    int stride = gridDim.x * blockDim.x;
    const float4* x4 = (const float4*)x;
    float4* h4 = (float4*)g_hpre;
    for (int i = blockIdx.x * blockDim.x + threadIdx.x; i < NNODE * DD / 4; i += stride) {
        float4 v = x4[i];
        v.x *= c; v.y *= c; v.z *= c; v.w *= c;
        h4[i] = v;
    }
}

// ---------------- 4) edge kernel: tf32 mma.sync GEMM + gather + relu + scatter ---
// Per CTA: 128 edges x 128 out, K=64. Warp w: rows [w*16, w*16+16), all 128 cols.
// SMEM K-layout permuted so fragment pairs (k, k+4) are adjacent -> LDS.64 loads.
//   k = g*8 + t + h*4  (g=k/8, t=k%4, h=(k%8)/4)  stored at  row*EPAD + g*8 + t*2 + h
#define EPAD 72
#define DPAD 132
#define SM_IDX_OFF (2 * 128 * EPAD)                 // in floats
#define SM_EDGE_TOTAL (SM_IDX_OFF * 4 + 256 * 4)    // bytes

__global__ __launch_bounds__(256, 2) void k_edge(const float* __restrict__ ea,
                                                 const float* __restrict__ x,
                                                 const float* __restrict__ be,
                                                 const float* __restrict__ We) {
    extern __shared__ float sm[];
    uint32_t* sA = (uint32_t*)sm;                    // [128][72] tf32 bits, permuted
    uint32_t* sB = (uint32_t*)(sm + 128 * EPAD);     // [128][72] tf32 bits, permuted
    float* sD = sm;                                  // [128][132] fp32, overlaps tiles
    int* sSrc = (int*)(sm + SM_IDX_OFF);
    int* sDst = sSrc + 128;

    int tid = threadIdx.x;
    int wid = tid >> 5;
    int lane = tid & 31;
    int gid = lane >> 2, tig = lane & 3;
    int e0 = blockIdx.x * 128;

    // tile fill: tf32 convert + K-permute (4 scalar STS per float4)
#pragma unroll
    for (int r = 0; r < 8; r++) {
        int i = tid + 256 * r;             // 0..2047
        int row = i >> 4, c4 = i & 15;
        int g = c4 >> 1, h = c4 & 1;
        int base = row * EPAD + g * 8 + h;
        float4 va = *(const float4*)(ea + (size_t)(e0 + row) * DE + c4 * 4);
        sA[base + 0] = f2tf(va.x);
        sA[base + 2] = f2tf(va.y);
        sA[base + 4] = f2tf(va.z);
        sA[base + 6] = f2tf(va.w);
        float4 vb = *(const float4*)(We + (size_t)row * DE + c4 * 4);
        sB[base + 0] = f2tf(vb.x);
        sB[base + 2] = f2tf(vb.y);
        sB[base + 4] = f2tf(vb.z);
        sB[base + 6] = f2tf(vb.w);
    }
    if (tid < 128) { sSrc[tid] = g_src[e0 + tid]; sDst[tid] = g_dst[e0 + tid]; }
    __syncthreads();

    float acc[16][4];
#pragma unroll
    for (int nt = 0; nt < 16; nt++)
#pragma unroll
        for (int j = 0; j < 4; j++) acc[nt][j] = 0.f;

    int arow_off = (wid * 16 + gid) * EPAD;
#pragma unroll
    for (int ks = 0; ks < 8; ks++) {
        int kbase = ks * 8 + tig * 2;
        // A fragments: two LDS.64 (pairs (k0+tig, k0+tig+4))
        uint2 a01 = *(const uint2*)&sA[arow_off + kbase];
        uint2 a23 = *(const uint2*)&sA[arow_off + 8 * EPAD + kbase];
        uint32_t afrag[4] = {a01.x, a23.x, a01.y, a23.y};
        // B fragments: 16 LDS.64, batched so loads pipeline ahead of the mmas
        uint2 bfrag[16];
#pragma unroll
        for (int nt = 0; nt < 16; nt++)
            bfrag[nt] = *(const uint2*)&sB[(nt * 8 + gid) * EPAD + kbase];
#pragma unroll
        for (int nt = 0; nt < 16; nt++)
            mma_tf32(acc[nt], afrag, bfrag[nt].x, bfrag[nt].y);
    }
    __syncthreads();   // all warps done reading tiles; sD may now overwrite them

    // stage accumulators to smem in natural [edge][col] layout
#pragma unroll
    for (int nt = 0; nt < 16; nt++) {
        int col = nt * 8 + 2 * tig;
        int row = wid * 16 + gid;
        *(float2*)&sD[row * DPAD + col] = make_float2(acc[nt][0], acc[nt][1]);
        *(float2*)&sD[(row + 8) * DPAD + col] = make_float2(acc[nt][2], acc[nt][3]);
    }
    __syncthreads();

    // epilogue: warp w -> edges (w&3)*32+lane, column half (w>>2)*64
    int erow = (wid & 3) * 32 + lane;
    int c0 = (wid >> 2) * 64;
    int s = sSrc[erow];
    int d = sDst[erow];
    const float4* xr = (const float4*)(x + (size_t)s * DD + c0);
    const float4* ber = (const float4*)(be + c0);
    const float* drow = &sD[erow * DPAD + c0];
    float* dptr = g_hpre + (size_t)d * DD + c0;
#pragma unroll
    for (int c4 = 0; c4 < 16; c4++) {
        float4 dv = *(const float4*)&drow[c4 * 4];
        float4 xv = xr[c4];
        float4 bv = ber[c4];
        float m0 = fmaxf(dv.x + xv.x + bv.x, 0.f);
        float m1 = fmaxf(dv.y + xv.y + bv.y, 0.f);
        float m2 = fmaxf(dv.z + xv.z + bv.z, 0.f);
        float m3 = fmaxf(dv.w + xv.w + bv.w, 0.f);
        red_add_v4(dptr + c4 * 4, m0, m1, m2, m3);
    }
}

// ---------------- 5) GEMM1: y1 = hpre @ W1^T + b1, accumulate BN stats ----------
__global__ __launch_bounds__(256) void k_gemm1(const float* __restrict__ bias) {
    __shared__ float As[128 * 36];
    __shared__ float Bs[32 * 128];
    __shared__ float sSum[128];
    __shared__ float sSq[128];
    int tid = threadIdx.x;
    int m0 = blockIdx.x * 128;
    int n0 = blockIdx.y * 128;
    int tx8 = (tid & 15) * 8;
    int ty8 = (tid >> 4) * 8;
    unsigned long long acc[8][4];
#pragma unroll
    for (int i = 0; i < 8; i++)
#pragma unroll
        for (int j = 0; j < 4; j++) acc[i][j] = 0ull;

    for (int kc = 0; kc < DD; kc += 32) {
#pragma unroll
        for (int r = 0; r < 4; r++) {
            int idx = tid + 256 * r;
            int row = idx >> 3, c4 = idx & 7;
            int m = m0 + row;
            float4 v = make_float4(0.f, 0.f, 0.f, 0.f);
            if (m < NNODE) v = *(const float4*)&g_hpre[(size_t)m * DD + kc + c4 * 4];
            *(float4*)&As[row * 36 + c4 * 4] = v;
        }
#pragma unroll
        for (int r = 0; r < 4; r++) {
            int idx = tid + 256 * r;
            int k = idx >> 5, c4 = idx & 31;
            *(float4*)&Bs[k * 128 + c4 * 4] = *(const float4*)&g_W1T[(size_t)(kc + k) * HH + n0 + c4 * 4];
        }
        __syncthreads();
#pragma unroll
        for (int k = 0; k < 32; k += 4) {
            float4 a4[8];
#pragma unroll
            for (int i = 0; i < 8; i++) a4[i] = *(const float4*)&As[(ty8 + i) * 36 + k];
#pragma unroll
            for (int kk = 0; kk < 4; kk++) {
                const unsigned long long* bp = (const unsigned long long*)&Bs[(k + kk) * 128 + tx8];
                unsigned long long b0 = bp[0], b1 = bp[1], b2 = bp[2], b3 = bp[3];
#pragma unroll
                for (int i = 0; i < 8; i++) {
                    unsigned long long a2 = bcast2(((const float*)&a4[i])[kk]);
                    ffma2(acc[i][0], a2, b0);
                    ffma2(acc[i][1], a2, b1);
                    ffma2(acc[i][2], a2, b2);
                    ffma2(acc[i][3], a2, b3);
                }
            }
        }
        __syncthreads();
    }

    float4 bb0 = *(const float4*)&bias[n0 + tx8];
    float4 bb1 = *(const float4*)&bias[n0 + tx8 + 4];
    float bv[8] = {bb0.x, bb0.y, bb0.z, bb0.w, bb1.x, bb1.y, bb1.z, bb1.w};
    float lsum[8], lsq[8];
#pragma unroll
    for (int j = 0; j < 8; j++) { lsum[j] = 0.f; lsq[j] = 0.f; }
#pragma unroll
    for (int i = 0; i < 8; i++) {
        int m = m0 + ty8 + i;
        if (m < NNODE) {
            float2 pr[4] = {up2(acc[i][0]), up2(acc[i][1]), up2(acc[i][2]), up2(acc[i][3])};
            float v[8];
#pragma unroll
            for (int j = 0; j < 8; j++) {
                float a = (j & 1) ? pr[j >> 1].y : pr[j >> 1].x;
                v[j] = a + bv[j];
                lsum[j] += v[j];
                lsq[j] += v[j] * v[j];
            }
            float4* o = (float4*)&g_y1[(size_t)m * HH + n0 + tx8];
            o[0] = make_float4(v[0], v[1], v[2], v[3]);
            o[1] = make_float4(v[4], v[5], v[6], v[7]);
        }
    }
    if (tid < 128) { sSum[tid] = 0.f; sSq[tid] = 0.f; }
    __syncthreads();
#pragma unroll
    for (int j = 0; j < 8; j++) {
        atomicAdd(&sSum[tx8 + j], lsum[j]);
        atomicAdd(&sSq[tx8 + j], lsq[j]);
    }
    __syncthreads();
    if (tid < 128) {
        atomicAdd(&g_sum1[n0 + tid], sSum[tid]);
        atomicAdd(&g_sq1[n0 + tid], sSq[tid]);
    }
}

// ---------------- 6) fold BN1 stats into scale/shift ----------------------------
__global__ void k_stat1(const float* __restrict__ g, const float* __restrict__ beta) {
    int j = threadIdx.x;
    if (j < HH) {
        float mu = g_sum1[j] / (float)NNODE;
        float var = g_sq1[j] / (float)NNODE - mu * mu;
        float sc = g[j] * rsqrtf(var + BN_EPS);
        g_scale1[j] = sc;
        g_shift1[j] = beta[j] - mu * sc;
    }
}

// ---------------- 7) GEMM2: out = relu(bn1(y1)) @ W2^T + b2, accumulate stats ---
__global__ __launch_bounds__(256) void k_gemm2(const float* __restrict__ bias,
                                               float* __restrict__ out) {
    __shared__ float As[128 * 36];
    __shared__ float Bs[32 * 128];
    __shared__ float sSum[128];
    __shared__ float sSq[128];
    int tid = threadIdx.x;
    int m0 = blockIdx.x * 128;
    int tx8 = (tid & 15) * 8;
    int ty8 = (tid >> 4) * 8;
    unsigned long long acc[8][4];
#pragma unroll
    for (int i = 0; i < 8; i++)
#pragma unroll
        for (int j = 0; j < 4; j++) acc[i][j] = 0ull;

    for (int kc = 0; kc < HH; kc += 32) {
#pragma unroll
        for (int r = 0; r < 4; r++) {
            int idx = tid + 256 * r;
            int row = idx >> 3, c4 = idx & 7;
            int m = m0 + row;
            int col = kc + c4 * 4;
            float4 v = make_float4(0.f, 0.f, 0.f, 0.f);
            if (m < NNODE) v = *(const float4*)&g_y1[(size_t)m * HH + col];
            float4 sc = *(const float4*)&g_scale1[col];
            float4 sh = *(const float4*)&g_shift1[col];
            v.x = fmaxf(fmaf(v.x, sc.x, sh.x), 0.f);
            v.y = fmaxf(fmaf(v.y, sc.y, sh.y), 0.f);
            v.z = fmaxf(fmaf(v.z, sc.z, sh.z), 0.f);
            v.w = fmaxf(fmaf(v.w, sc.w, sh.w), 0.f);
            *(float4*)&As[row * 36 + c4 * 4] = v;
        }
#pragma unroll
        for (int r = 0; r < 4; r++) {
            int idx = tid + 256 * r;
            int k = idx >> 5, c4 = idx & 31;
            *(float4*)&Bs[k * 128 + c4 * 4] = *(const float4*)&g_W2T[(size_t)(kc + k) * DD + c4 * 4];
        }
        __syncthreads();
#pragma unroll
        for (int k = 0; k < 32; k += 4) {
            float4 a4[8];
#pragma unroll
            for (int i = 0; i < 8; i++) a4[i] = *(const float4*)&As[(ty8 + i) * 36 + k];
#pragma unroll
            for (int kk = 0; kk < 4; kk++) {
                const unsigned long long* bp = (const unsigned long long*)&Bs[(k + kk) * 128 + tx8];
                unsigned long long b0 = bp[0], b1 = bp[1], b2 = bp[2], b3 = bp[3];
#pragma unroll
                for (int i = 0; i < 8; i++) {
                    unsigned long long a2 = bcast2(((const float*)&a4[i])[kk]);
                    ffma2(acc[i][0], a2, b0);
                    ffma2(acc[i][1], a2, b1);
                    ffma2(acc[i][2], a2, b2);
                    ffma2(acc[i][3], a2, b3);
                }
            }
        }
        __syncthreads();
    }

    float4 bb0 = *(const float4*)&bias[tx8];
    float4 bb1 = *(const float4*)&bias[tx8 + 4];
    float bv[8] = {bb0.x, bb0.y, bb0.z, bb0.w, bb1.x, bb1.y, bb1.z, bb1.w};
    float lsum[8], lsq[8];
#pragma unroll
    for (int j = 0; j < 8; j++) { lsum[j] = 0.f; lsq[j] = 0.f; }
#pragma unroll
    for (int i = 0; i < 8; i++) {
        int m = m0 + ty8 + i;
        if (m < NNODE) {
            float2 pr[4] = {up2(acc[i][0]), up2(acc[i][1]), up2(acc[i][2]), up2(acc[i][3])};
            float v[8];
#pragma unroll
            for (int j = 0; j < 8; j++) {
                float a = (j & 1) ? pr[j >> 1].y : pr[j >> 1].x;
                v[j] = a + bv[j];
                lsum[j] += v[j];
                lsq[j] += v[j] * v[j];
            }
            float4* o = (float4*)&out[(size_t)m * DD + tx8];
            o[0] = make_float4(v[0], v[1], v[2], v[3]);
            o[1] = make_float4(v[4], v[5], v[6], v[7]);
        }
    }
    if (tid < 128) { sSum[tid] = 0.f; sSq[tid] = 0.f; }
    __syncthreads();
#pragma unroll
    for (int j = 0; j < 8; j++) {
        atomicAdd(&sSum[tx8 + j], lsum[j]);
        atomicAdd(&sSq[tx8 + j], lsq[j]);
    }
    __syncthreads();
    if (tid < 128) {
        atomicAdd(&g_sum2[tid], sSum[tid]);
        atomicAdd(&g_sq2[tid], sSq[tid]);
    }
}

// ---------------- 8) fold BN2 stats --------------------------------------------
__global__ void k_stat2(const float* __restrict__ g, const float* __restrict__ beta) {
    int j = threadIdx.x;
    if (j < DD) {
        float mu = g_sum2[j] / (float)NNODE;
        float var = g_sq2[j] / (float)NNODE - mu * mu;
        float sc = g[j] * rsqrtf(var + BN_EPS);
        g_scale2[j] = sc;
        g_shift2[j] = beta[j] - mu * sc;
    }
}

// ---------------- 9) final elementwise: out = relu(bn2(out)) --------------------
__global__ void k_final(float* __restrict__ out) {
    int stride = gridDim.x * blockDim.x;
    float4* o4 = (float4*)out;
    for (int i = blockIdx.x * blockDim.x + threadIdx.x; i < NNODE * DD / 4; i += stride) {
        int col = (i & 31) * 4;
        float4 sc = *(const float4*)&g_scale2[col];
        float4 sh = *(const float4*)&g_shift2[col];
        float4 v = o4[i];
        v.x = fmaxf(fmaf(v.x, sc.x, sh.x), 0.f);
        v.y = fmaxf(fmaf(v.y, sc.y, sh.y), 0.f);
        v.z = fmaxf(fmaf(v.z, sc.z, sh.z), 0.f);
        v.w = fmaxf(fmaf(v.w, sc.w, sh.w), 0.f);
        o4[i] = v;
    }
}

// ---------------- launcher ------------------------------------------------------
extern "C" void kernel_launch(void* const* d_in, const int* in_sizes, int n_in,
                              void* d_out, int out_size) {
    const float* x   = (const float*)d_in[0];
    const int*   ei  = (const int*)d_in[1];
    const float* ea  = (const float*)d_in[2];
    const float* We  = (const float*)d_in[3];
    const float* be  = (const float*)d_in[4];
    const float* W1  = (const float*)d_in[5];
    const float* b1  = (const float*)d_in[6];
    const float* g1  = (const float*)d_in[7];
    const float* be1 = (const float*)d_in[8];
    const float* W2  = (const float*)d_in[9];
    const float* b2  = (const float*)d_in[10];
    const float* g2  = (const float*)d_in[11];
    const float* be2 = (const float*)d_in[12];
    const float* eps = (const float*)d_in[13];
    float* out = (float*)d_out;

    cudaFuncSetAttribute(k_edge, cudaFuncAttributeMaxDynamicSharedMemorySize, SM_EDGE_TOTAL);

    k_decode<<<1024, 256>>>(ei);
    k_misc<<<64, 256>>>(W1, W2);
    k_hpre<<<2048, 256>>>(x, eps);
    k_edge<<<NEDGE / 128, 256, SM_EDGE_TOTAL>>>(ea, x, be, We);
    dim3 g1grid((NNODE + 127) / 128, 2);
    k_gemm1<<<g1grid, 256>>>(b1);
    k_stat1<<<1, 256>>>(g1, be1);
    k_gemm2<<<(NNODE + 127) / 128, 256>>>(b2, out);
    k_stat2<<<1, 128>>>(g2, be2);
    k_final<<<2048, 256>>>(out);
}

// round 12
// speedup vs baseline: 1.4736x; 1.3869x over previous
#include <cuda_runtime.h>
#include <cstdint>
#include <cstddef>

#define NNODE 50000
#define NEDGE 800000
#define DD 128     // node feature dim
#define DE 64      // edge feature dim
#define HH 256     // hidden dim (2*D)
#define BN_EPS 1e-5f

// ---------------- device scratch (static; no allocations allowed) ----------------
__device__ float g_hpre[(size_t)NNODE * DD];
__device__ float g_y1[(size_t)NNODE * HH];
__device__ float g_W1T[DD * HH];
__device__ float g_W2T[HH * DD];
__device__ int   g_src[NEDGE];
__device__ int   g_dst[NEDGE];
__device__ float g_sum1[HH], g_sq1[HH], g_sum2[DD], g_sq2[DD];
__device__ float g_scale1[HH], g_shift1[HH], g_scale2[DD], g_shift2[DD];

__device__ __forceinline__ void red_add_v4(float* a, float x, float y, float z, float w) {
    asm volatile("red.global.add.v4.f32 [%0], {%1,%2,%3,%4};"
                 :: "l"(a), "f"(x), "f"(y), "f"(z), "f"(w) : "memory");
}

// packed fp32x2 helpers (sm_100+)
__device__ __forceinline__ unsigned long long bcast2(float a) {
    unsigned long long r;
    unsigned int u = __float_as_uint(a);
    asm("mov.b64 %0, {%1, %1};" : "=l"(r) : "r"(u));
    return r;
}
__device__ __forceinline__ void ffma2(unsigned long long& d, unsigned long long a,
                                      unsigned long long b) {
    asm("fma.rn.f32x2 %0, %1, %2, %0;" : "+l"(d) : "l"(a), "l"(b));
}
__device__ __forceinline__ float2 up2(unsigned long long v) {
    float2 f;
    f.x = __uint_as_float((unsigned int)v);
    f.y = __uint_as_float((unsigned int)(v >> 32));
    return f;
}

// ---------------- 1) decode edge_index (int64 or int32, detected on device) -----
__global__ void k_decode(const int* __restrict__ ei) {
    bool is64 = ((ei[1] | ei[3] | ei[5] | ei[7] | ei[9] | ei[11] | ei[13] | ei[15]) == 0);
    int stride = gridDim.x * blockDim.x;
    for (int i = blockIdx.x * blockDim.x + threadIdx.x; i < NEDGE; i += stride) {
        int s, d;
        if (is64) {
            const long long* p = (const long long*)ei;
            s = (int)p[i];
            d = (int)p[NEDGE + i];
        } else {
            s = ei[i];
            d = ei[NEDGE + i];
        }
        g_src[i] = s;
        g_dst[i] = d;
    }
}

// ---------------- 2) transposes + zero stats ------------------------------------
__global__ void k_misc(const float* __restrict__ W1, const float* __restrict__ W2) {
    int stride = gridDim.x * blockDim.x;
    int t0 = blockIdx.x * blockDim.x + threadIdx.x;
    for (int i = t0; i < DD * HH; i += stride) { int k = i / HH, j = i % HH; g_W1T[i] = W1[j * DD + k]; }
    for (int i = t0; i < HH * DD; i += stride) { int k = i / DD, j = i % DD; g_W2T[i] = W2[j * HH + k]; }
    for (int i = t0; i < HH; i += stride) { g_sum1[i] = 0.f; g_sq1[i] = 0.f; }
    for (int i = t0; i < DD; i += stride) { g_sum2[i] = 0.f; g_sq2[i] = 0.f; }
}

// ---------------- 3) hpre = (1+eps) * x -----------------------------------------
__global__ void k_hpre(const float* __restrict__ x, const float* __restrict__ epsp) {
    float c = 1.0f + *epsp;
    int stride = gridDim.x * blockDim.x;
    const float4* x4 = (const float4*)x;
    float4* h4 = (float4*)g_hpre;
    for (int i = blockIdx.x * blockDim.x + threadIdx.x; i < NNODE * DD / 4; i += stride) {
        float4 v = x4[i];
        v.x *= c; v.y *= c; v.z *= c; v.w *= c;
        h4[i] = v;
    }
}

// ---------------- 4) edge kernel: FFMA2 GEMM (8x16 tile) + gather + scatter ------
// CTA: 256 edges x 128 cols, K=64. 256 threads = 32(ty, 8 edges each) x 8(tx, 16 cols each).
// bytes/FMA = 0.75 -> FMA-bound (vs 1.0 co-limit of the 8x8 tile).
// sA: [256][80]: 64 data + 12 max rotation + 4 slack. Per-8-row-group 16B rotation
//     keeps the 4 distinct A row-addresses per warp on disjoint bank groups; AEPAD=80
//     guarantees rot+63 <= 75 < 80 so rotated rows NEVER collide with the next row
//     (the r11 bug: AEPAD=68 let rot=12 rows alias the next row's k=0..7).
// sW: [64][132] with q-interleaved columns -> B warp-loads tile all 32 banks exactly once.
#define AEPAD 80
#define WPAD 132
#define SM_A_FLOATS (256 * AEPAD)                   // 20480
#define SM_W_FLOATS (64 * WPAD)                     // 8448
#define SM_IDX_F (SM_A_FLOATS + SM_W_FLOATS)
#define SM_EDGE_TOTAL ((SM_IDX_F + 512) * 4)        // ~115 KB

__global__ __launch_bounds__(256, 1) void k_edge(const float* __restrict__ ea,
                                                 const float* __restrict__ x,
                                                 const float* __restrict__ be,
                                                 const float* __restrict__ We) {
    extern __shared__ float sm[];
    float* sA = sm;
    float* sW = sm + SM_A_FLOATS;
    int* sSrc = (int*)(sm + SM_IDX_F);
    int* sDst = sSrc + 256;

    int tid = threadIdx.x;
    int tx = tid & 7;          // col group: 16 cols at tx*16
    int ty = tid >> 3;         // edge group: 8 edges at ty*8
    int e0 = blockIdx.x * 256;

    // fill A tile: 256 edges x 64 k, rotated rows (rot = ((row>>3)&3)*4 floats)
#pragma unroll
    for (int r = 0; r < 16; r++) {
        int i = tid + 256 * r;
        int row = i >> 4, c4 = i & 15;
        float4 v = *(const float4*)(ea + (size_t)(e0 + row) * DE + c4 * 4);
        *(float4*)&sA[row * AEPAD + ((row >> 3) & 3) * 4 + c4 * 4] = v;
    }
    // fill W tile: We[j][k] -> sW[k][perm(j)], perm: j -> q(j)*32 + (j/16)*4 + (j%4)
#pragma unroll
    for (int r = 0; r < 8; r++) {
        int i = tid + 256 * r;
        int j = i >> 4, c4 = i & 15;
        float4 v = *(const float4*)(We + (size_t)j * DE + c4 * 4);
        int base = ((j & 15) >> 2) * 32 + (j >> 4) * 4 + (j & 3);
        sW[(c4 * 4 + 0) * WPAD + base] = v.x;
        sW[(c4 * 4 + 1) * WPAD + base] = v.y;
        sW[(c4 * 4 + 2) * WPAD + base] = v.z;
        sW[(c4 * 4 + 3) * WPAD + base] = v.w;
    }
    sSrc[tid] = g_src[e0 + tid];
    sDst[tid] = g_dst[e0 + tid];
    __syncthreads();

    unsigned long long acc[8][8];
#pragma unroll
    for (int i = 0; i < 8; i++)
#pragma unroll
        for (int j = 0; j < 8; j++) acc[i][j] = 0ull;

    int ty8 = ty * 8;
    int ash = (ty & 3) * 4;             // constant row rotation for this thread's 8 rows
    const float* aBase = &sA[ty8 * AEPAD + ash];
    const float* wBase = &sW[tx * 4];

#pragma unroll 2
    for (int k = 0; k < DE; k += 4) {
        float4 a4[8];
#pragma unroll
        for (int i = 0; i < 8; i++)
            a4[i] = *(const float4*)(aBase + i * AEPAD + k);
#pragma unroll
        for (int kk = 0; kk < 4; kk++) {
            const float* wrow = wBase + (k + kk) * WPAD;
            unsigned long long b[8];
#pragma unroll
            for (int q = 0; q < 4; q++) {
                ulonglong2 t = *(const ulonglong2*)(wrow + q * 32);
                b[2 * q] = t.x;
                b[2 * q + 1] = t.y;
            }
#pragma unroll
            for (int i = 0; i < 8; i++) {
                unsigned long long a2 = bcast2(((const float*)&a4[i])[kk]);
                ffma2(acc[i][0], a2, b[0]);
                ffma2(acc[i][1], a2, b[1]);
                ffma2(acc[i][2], a2, b[2]);
                ffma2(acc[i][3], a2, b[3]);
                ffma2(acc[i][4], a2, b[4]);
                ffma2(acc[i][5], a2, b[5]);
                ffma2(acc[i][6], a2, b[6]);
                ffma2(acc[i][7], a2, b[7]);
            }
        }
    }

    // epilogue: per edge, add gathered x[src] + bias, relu, scatter-add to hpre[dst]
    const float4* ber = (const float4*)(be + tx * 16);
    float4 bvq[4] = {ber[0], ber[1], ber[2], ber[3]};
#pragma unroll
    for (int i = 0; i < 8; i++) {
        int e = ty8 + i;
        int s = sSrc[e];
        int d = sDst[e];
        const float4* xr = (const float4*)(x + (size_t)s * DD + tx * 16);
        float* dptr = g_hpre + (size_t)d * DD + tx * 16;
#pragma unroll
        for (int q = 0; q < 4; q++) {
            float2 p0 = up2(acc[i][2 * q]);
            float2 p1 = up2(acc[i][2 * q + 1]);
            float4 xv = xr[q];
            float4 bq = bvq[q];
            red_add_v4(dptr + q * 4,
                       fmaxf(p0.x + xv.x + bq.x, 0.f),
                       fmaxf(p0.y + xv.y + bq.y, 0.f),
                       fmaxf(p1.x + xv.z + bq.z, 0.f),
                       fmaxf(p1.y + xv.w + bq.w, 0.f));
        }
    }
}

// ---------------- 5) GEMM1: y1 = hpre @ W1^T + b1, accumulate BN stats ----------
__global__ __launch_bounds__(256) void k_gemm1(const float* __restrict__ bias) {
    __shared__ float As[128 * 36];
    __shared__ float Bs[32 * 128];
    __shared__ float sSum[128];
    __shared__ float sSq[128];
    int tid = threadIdx.x;
    int m0 = blockIdx.x * 128;
    int n0 = blockIdx.y * 128;
    int tx8 = (tid & 15) * 8;
    int ty8 = (tid >> 4) * 8;
    unsigned long long acc[8][4];
#pragma unroll
    for (int i = 0; i < 8; i++)
#pragma unroll
        for (int j = 0; j < 4; j++) acc[i][j] = 0ull;

    for (int kc = 0; kc < DD; kc += 32) {
#pragma unroll
        for (int r = 0; r < 4; r++) {
            int idx = tid + 256 * r;
            int row = idx >> 3, c4 = idx & 7;
            int m = m0 + row;
            float4 v = make_float4(0.f, 0.f, 0.f, 0.f);
            if (m < NNODE) v = *(const float4*)&g_hpre[(size_t)m * DD + kc + c4 * 4];
            *(float4*)&As[row * 36 + c4 * 4] = v;
        }
#pragma unroll
        for (int r = 0; r < 4; r++) {
            int idx = tid + 256 * r;
            int k = idx >> 5, c4 = idx & 31;
            *(float4*)&Bs[k * 128 + c4 * 4] = *(const float4*)&g_W1T[(size_t)(kc + k) * HH + n0 + c4 * 4];
        }
        __syncthreads();
#pragma unroll
        for (int k = 0; k < 32; k += 4) {
            float4 a4[8];
#pragma unroll
            for (int i = 0; i < 8; i++) a4[i] = *(const float4*)&As[(ty8 + i) * 36 + k];
#pragma unroll
            for (int kk = 0; kk < 4; kk++) {
                const unsigned long long* bp = (const unsigned long long*)&Bs[(k + kk) * 128 + tx8];
                unsigned long long b0 = bp[0], b1 = bp[1], b2 = bp[2], b3 = bp[3];
#pragma unroll
                for (int i = 0; i < 8; i++) {
                    unsigned long long a2 = bcast2(((const float*)&a4[i])[kk]);
                    ffma2(acc[i][0], a2, b0);
                    ffma2(acc[i][1], a2, b1);
                    ffma2(acc[i][2], a2, b2);
                    ffma2(acc[i][3], a2, b3);
                }
            }
        }
        __syncthreads();
    }

    float4 bb0 = *(const float4*)&bias[n0 + tx8];
    float4 bb1 = *(const float4*)&bias[n0 + tx8 + 4];
    float bv[8] = {bb0.x, bb0.y, bb0.z, bb0.w, bb1.x, bb1.y, bb1.z, bb1.w};
    float lsum[8], lsq[8];
#pragma unroll
    for (int j = 0; j < 8; j++) { lsum[j] = 0.f; lsq[j] = 0.f; }
#pragma unroll
    for (int i = 0; i < 8; i++) {
        int m = m0 + ty8 + i;
        if (m < NNODE) {
            float2 pr[4] = {up2(acc[i][0]), up2(acc[i][1]), up2(acc[i][2]), up2(acc[i][3])};
            float v[8];
#pragma unroll
            for (int j = 0; j < 8; j++) {
                float a = (j & 1) ? pr[j >> 1].y : pr[j >> 1].x;
                v[j] = a + bv[j];
                lsum[j] += v[j];
                lsq[j] += v[j] * v[j];
            }
            float4* o = (float4*)&g_y1[(size_t)m * HH + n0 + tx8];
            o[0] = make_float4(v[0], v[1], v[2], v[3]);
            o[1] = make_float4(v[4], v[5], v[6], v[7]);
        }
    }
    if (tid < 128) { sSum[tid] = 0.f; sSq[tid] = 0.f; }
    __syncthreads();
#pragma unroll
    for (int j = 0; j < 8; j++) {
        atomicAdd(&sSum[tx8 + j], lsum[j]);
        atomicAdd(&sSq[tx8 + j], lsq[j]);
    }
    __syncthreads();
    if (tid < 128) {
        atomicAdd(&g_sum1[n0 + tid], sSum[tid]);
        atomicAdd(&g_sq1[n0 + tid], sSq[tid]);
    }
}

// ---------------- 6) fold BN1 stats into scale/shift ----------------------------
__global__ void k_stat1(const float* __restrict__ g, const float* __restrict__ beta) {
    int j = threadIdx.x;
    if (j < HH) {
        float mu = g_sum1[j] / (float)NNODE;
        float var = g_sq1[j] / (float)NNODE - mu * mu;
        float sc = g[j] * rsqrtf(var + BN_EPS);
        g_scale1[j] = sc;
        g_shift1[j] = beta[j] - mu * sc;
    }
}

// ---------------- 7) GEMM2: out = relu(bn1(y1)) @ W2^T + b2, accumulate stats ---
__global__ __launch_bounds__(256) void k_gemm2(const float* __restrict__ bias,
                                               float* __restrict__ out) {
    __shared__ float As[128 * 36];
    __shared__ float Bs[32 * 128];
    __shared__ float sSum[128];
    __shared__ float sSq[128];
    int tid = threadIdx.x;
    int m0 = blockIdx.x * 128;
    int tx8 = (tid & 15) * 8;
    int ty8 = (tid >> 4) * 8;
    unsigned long long acc[8][4];
#pragma unroll
    for (int i = 0; i < 8; i++)
#pragma unroll
        for (int j = 0; j < 4; j++) acc[i][j] = 0ull;

    for (int kc = 0; kc < HH; kc += 32) {
#pragma unroll
        for (int r = 0; r < 4; r++) {
            int idx = tid + 256 * r;
            int row = idx >> 3, c4 = idx & 7;
            int m = m0 + row;
            int col = kc + c4 * 4;
            float4 v = make_float4(0.f, 0.f, 0.f, 0.f);
            if (m < NNODE) v = *(const float4*)&g_y1[(size_t)m * HH + col];
            float4 sc = *(const float4*)&g_scale1[col];
            float4 sh = *(const float4*)&g_shift1[col];
            v.x = fmaxf(fmaf(v.x, sc.x, sh.x), 0.f);
            v.y = fmaxf(fmaf(v.y, sc.y, sh.y), 0.f);
            v.z = fmaxf(fmaf(v.z, sc.z, sh.z), 0.f);
            v.w = fmaxf(fmaf(v.w, sc.w, sh.w), 0.f);
            *(float4*)&As[row * 36 + c4 * 4] = v;
        }
#pragma unroll
        for (int r = 0; r < 4; r++) {
            int idx = tid + 256 * r;
            int k = idx >> 5, c4 = idx & 31;
            *(float4*)&Bs[k * 128 + c4 * 4] = *(const float4*)&g_W2T[(size_t)(kc + k) * DD + c4 * 4];
        }
        __syncthreads();
#pragma unroll
        for (int k = 0; k < 32; k += 4) {
            float4 a4[8];
#pragma unroll
            for (int i = 0; i < 8; i++) a4[i] = *(const float4*)&As[(ty8 + i) * 36 + k];
#pragma unroll
            for (int kk = 0; kk < 4; kk++) {
                const unsigned long long* bp = (const unsigned long long*)&Bs[(k + kk) * 128 + tx8];
                unsigned long long b0 = bp[0], b1 = bp[1], b2 = bp[2], b3 = bp[3];
#pragma unroll
                for (int i = 0; i < 8; i++) {
                    unsigned long long a2 = bcast2(((const float*)&a4[i])[kk]);
                    ffma2(acc[i][0], a2, b0);
                    ffma2(acc[i][1], a2, b1);
                    ffma2(acc[i][2], a2, b2);
                    ffma2(acc[i][3], a2, b3);
                }
            }
        }
        __syncthreads();
    }

    float4 bb0 = *(const float4*)&bias[tx8];
    float4 bb1 = *(const float4*)&bias[tx8 + 4];
    float bv[8] = {bb0.x, bb0.y, bb0.z, bb0.w, bb1.x, bb1.y, bb1.z, bb1.w};
    float lsum[8], lsq[8];
#pragma unroll
    for (int j = 0; j < 8; j++) { lsum[j] = 0.f; lsq[j] = 0.f; }
#pragma unroll
    for (int i = 0; i < 8; i++) {
        int m = m0 + ty8 + i;
        if (m < NNODE) {
            float2 pr[4] = {up2(acc[i][0]), up2(acc[i][1]), up2(acc[i][2]), up2(acc[i][3])};
            float v[8];
#pragma unroll
            for (int j = 0; j < 8; j++) {
                float a = (j & 1) ? pr[j >> 1].y : pr[j >> 1].x;
                v[j] = a + bv[j];
                lsum[j] += v[j];
                lsq[j] += v[j] * v[j];
            }
            float4* o = (float4*)&out[(size_t)m * DD + tx8];
            o[0] = make_float4(v[0], v[1], v[2], v[3]);
            o[1] = make_float4(v[4], v[5], v[6], v[7]);
        }
    }
    if (tid < 128) { sSum[tid] = 0.f; sSq[tid] = 0.f; }
    __syncthreads();
#pragma unroll
    for (int j = 0; j < 8; j++) {
        atomicAdd(&sSum[tx8 + j], lsum[j]);
        atomicAdd(&sSq[tx8 + j], lsq[j]);
    }
    __syncthreads();
    if (tid < 128) {
        atomicAdd(&g_sum2[tid], sSum[tid]);
        atomicAdd(&g_sq2[tid], sSq[tid]);
    }
}

// ---------------- 8) fold BN2 stats --------------------------------------------
__global__ void k_stat2(const float* __restrict__ g, const float* __restrict__ beta) {
    int j = threadIdx.x;
    if (j < DD) {
        float mu = g_sum2[j] / (float)NNODE;
        float var = g_sq2[j] / (float)NNODE - mu * mu;
        float sc = g[j] * rsqrtf(var + BN_EPS);
        g_scale2[j] = sc;
        g_shift2[j] = beta[j] - mu * sc;
    }
}

// ---------------- 9) final elementwise: out = relu(bn2(out)) --------------------
__global__ void k_final(float* __restrict__ out) {
    int stride = gridDim.x * blockDim.x;
    float4* o4 = (float4*)out;
    for (int i = blockIdx.x * blockDim.x + threadIdx.x; i < NNODE * DD / 4; i += stride) {
        int col = (i & 31) * 4;
        float4 sc = *(const float4*)&g_scale2[col];
        float4 sh = *(const float4*)&g_shift2[col];
        float4 v = o4[i];
        v.x = fmaxf(fmaf(v.x, sc.x, sh.x), 0.f);
        v.y = fmaxf(fmaf(v.y, sc.y, sh.y), 0.f);
        v.z = fmaxf(fmaf(v.z, sc.z, sh.z), 0.f);
        v.w = fmaxf(fmaf(v.w, sc.w, sh.w), 0.f);
        o4[i] = v;
    }
}

// ---------------- launcher ------------------------------------------------------
extern "C" void kernel_launch(void* const* d_in, const int* in_sizes, int n_in,
                              void* d_out, int out_size) {
    const float* x   = (const float*)d_in[0];
    const int*   ei  = (const int*)d_in[1];
    const float* ea  = (const float*)d_in[2];
    const float* We  = (const float*)d_in[3];
    const float* be  = (const float*)d_in[4];
    const float* W1  = (const float*)d_in[5];
    const float* b1  = (const float*)d_in[6];
    const float* g1  = (const float*)d_in[7];
    const float* be1 = (const float*)d_in[8];
    const float* W2  = (const float*)d_in[9];
    const float* b2  = (const float*)d_in[10];
    const float* g2  = (const float*)d_in[11];
    const float* be2 = (const float*)d_in[12];
    const float* eps = (const float*)d_in[13];
    float* out = (float*)d_out;

    cudaFuncSetAttribute(k_edge, cudaFuncAttributeMaxDynamicSharedMemorySize, SM_EDGE_TOTAL);

    k_decode<<<1024, 256>>>(ei);
    k_misc<<<64, 256>>>(W1, W2);
    k_hpre<<<2048, 256>>>(x, eps);
    k_edge<<<NEDGE / 256, 256, SM_EDGE_TOTAL>>>(ea, x, be, We);
    dim3 g1grid((NNODE + 127) / 128, 2);
    k_gemm1<<<g1grid, 256>>>(b1);
    k_stat1<<<1, 256>>>(g1, be1);
    k_gemm2<<<(NNODE + 127) / 128, 256>>>(b2, out);
    k_stat2<<<1, 128>>>(g2, be2);
    k_final<<<2048, 256>>>(out);
}

// round 14
// speedup vs baseline: 1.8459x; 1.2527x over previous
#include <cuda_runtime.h>
#include <cstdint>
#include <cstddef>

#define NNODE 50000
#define NEDGE 800000
#define DD 128     // node feature dim
#define DE 64      // edge feature dim
#define HH 256     // hidden dim (2*D)
#define BN_EPS 1e-5f

// ---------------- device scratch (static; no allocations allowed) ----------------
__device__ float g_hpre[(size_t)NNODE * DD];
__device__ float g_y1[(size_t)NNODE * HH];
__device__ float g_WeT[DE * DD];
__device__ float g_W1T[DD * HH];
__device__ float g_W2T[HH * DD];
__device__ int   g_src[NEDGE];
__device__ int   g_dst[NEDGE];
__device__ float g_sum1[HH], g_sq1[HH], g_sum2[DD], g_sq2[DD];
__device__ float g_scale1[HH], g_shift1[HH], g_scale2[DD], g_shift2[DD];

__device__ __forceinline__ void red_add_v4(float* a, float x, float y, float z, float w) {
    asm volatile("red.global.add.v4.f32 [%0], {%1,%2,%3,%4};"
                 :: "l"(a), "f"(x), "f"(y), "f"(z), "f"(w) : "memory");
}

// packed fp32x2 helpers (sm_100+)
__device__ __forceinline__ unsigned long long bcast2(float a) {
    unsigned long long r;
    unsigned int u = __float_as_uint(a);
    asm("mov.b64 %0, {%1, %1};" : "=l"(r) : "r"(u));
    return r;
}
__device__ __forceinline__ void ffma2(unsigned long long& d, unsigned long long a,
                                      unsigned long long b) {
    asm("fma.rn.f32x2 %0, %1, %2, %0;" : "+l"(d) : "l"(a), "l"(b));
}
__device__ __forceinline__ float2 up2(unsigned long long v) {
    float2 f;
    f.x = __uint_as_float((unsigned int)v);
    f.y = __uint_as_float((unsigned int)(v >> 32));
    return f;
}

// ---------------- 1) decode edge_index (int64 or int32, detected on device) -----
__global__ void k_decode(const int* __restrict__ ei) {
    bool is64 = ((ei[1] | ei[3] | ei[5] | ei[7] | ei[9] | ei[11] | ei[13] | ei[15]) == 0);
    int stride = gridDim.x * blockDim.x;
    for (int i = blockIdx.x * blockDim.x + threadIdx.x; i < NEDGE; i += stride) {
        int s, d;
        if (is64) {
            const long long* p = (const long long*)ei;
            s = (int)p[i];
            d = (int)p[NEDGE + i];
        } else {
            s = ei[i];
            d = ei[NEDGE + i];
        }
        g_src[i] = s;
        g_dst[i] = d;
    }
}

// ---------------- 2) transposes + zero stats ------------------------------------
__global__ void k_misc(const float* __restrict__ We, const float* __restrict__ W1,
                       const float* __restrict__ W2) {
    int stride = gridDim.x * blockDim.x;
    int t0 = blockIdx.x * blockDim.x + threadIdx.x;
    for (int i = t0; i < DE * DD; i += stride) { int k = i / DD, j = i % DD; g_WeT[i] = We[j * DE + k]; }
    for (int i = t0; i < DD * HH; i += stride) { int k = i / HH, j = i % HH; g_W1T[i] = W1[j * DD + k]; }
    for (int i = t0; i < HH * DD; i += stride) { int k = i / DD, j = i % DD; g_W2T[i] = W2[j * HH + k]; }
    for (int i = t0; i < HH; i += stride) { g_sum1[i] = 0.f; g_sq1[i] = 0.f; }
    for (int i = t0; i < DD; i += stride) { g_sum2[i] = 0.f; g_sq2[i] = 0.f; }
}

// ---------------- 3) hpre = (1+eps) * x -----------------------------------------
__global__ void k_hpre(const float* __restrict__ x, const float* __restrict__ epsp) {
    float c = 1.0f + *epsp;
    int stride = gridDim.x * blockDim.x;
    const float4* x4 = (const float4*)x;
    float4* h4 = (float4*)g_hpre;
    for (int i = blockIdx.x * blockDim.x + threadIdx.x; i < NNODE * DD / 4; i += stride) {
        float4 v = x4[i];
        v.x *= c; v.y *= c; v.z *= c; v.w *= c;
        h4[i] = v;
    }
}

// ---------------- 4) edge kernel: FFMA2 GEMM (8x8 tile, 2 CTAs/SM) ---------------
// Per CTA: 128 edges x 128 cols, K=64. Proven r3 layout; loop interchanged so B
// (b[4][4], 32 regs) is loop-invariant per k-chunk and A streams one float4 at a
// time -> ~115 regs -> 2 CTAs/SM (16 warps) for latency hiding.
#define SM_EDGE_TOTAL ((128 * DE + DE * DD + 256) * 4)   // 66560 B; x2 CTAs = 133 KB < 228 KB

__global__ __launch_bounds__(256, 2) void k_edge(const float* __restrict__ ea,
                                                 const float* __restrict__ x,
                                                 const float* __restrict__ be) {
    extern __shared__ float sm[];
    float* sEA = sm;                  // [128][64]
    float* sW  = sm + 128 * DE;       // [64][128]  (WeT layout)
    int* sSrc = (int*)(sm + 128 * DE + DE * DD);
    int* sDst = sSrc + 128;

    int tid = threadIdx.x;
    int e0 = blockIdx.x * 128;

    // linear, fully coalesced tile copies
    const float4* gA = (const float4*)(ea + (size_t)e0 * DE);
    float4* s4 = (float4*)sEA;
#pragma unroll
    for (int r = 0; r < 8; r++) s4[tid + 256 * r] = gA[tid + 256 * r];
    const float4* gW = (const float4*)g_WeT;
    float4* w4 = (float4*)sW;
#pragma unroll
    for (int r = 0; r < 8; r++) w4[tid + 256 * r] = gW[tid + 256 * r];
    if (tid < 128) { sSrc[tid] = g_src[e0 + tid]; sDst[tid] = g_dst[e0 + tid]; }
    __syncthreads();

    int tx8 = (tid & 15) * 8;   // output group
    int ty8 = (tid >> 4) * 8;   // edge group
    unsigned long long acc[8][4];
#pragma unroll
    for (int i = 0; i < 8; i++)
#pragma unroll
        for (int j = 0; j < 4; j++) acc[i][j] = 0ull;

#pragma unroll
    for (int k = 0; k < DE; k += 4) {
        // B rows k..k+3 for this thread's 8 columns: 16 ull (32 regs), loop-invariant
        unsigned long long b[4][4];
#pragma unroll
        for (int kk = 0; kk < 4; kk++) {
            const unsigned long long* bp = (const unsigned long long*)&sW[(k + kk) * DD + tx8];
            b[kk][0] = bp[0]; b[kk][1] = bp[1]; b[kk][2] = bp[2]; b[kk][3] = bp[3];
        }
#pragma unroll
        for (int i = 0; i < 8; i++) {
            float4 a4 = *(const float4*)&sEA[(ty8 + i) * DE + k];
#pragma unroll
            for (int kk = 0; kk < 4; kk++) {
                unsigned long long a2 = bcast2(((const float*)&a4)[kk]);
                ffma2(acc[i][0], a2, b[kk][0]);
                ffma2(acc[i][1], a2, b[kk][1]);
                ffma2(acc[i][2], a2, b[kk][2]);
                ffma2(acc[i][3], a2, b[kk][3]);
            }
        }
    }

    float4 be0 = *(const float4*)(be + tx8);
    float4 be1 = *(const float4*)(be + tx8 + 4);
#pragma unroll
    for (int i = 0; i < 8; i++) {
        int el = ty8 + i;
        int s = sSrc[el];
        int d = sDst[el];
        const float4* xr = (const float4*)(x + (size_t)s * DD + tx8);
        float4 x0 = xr[0], x1 = xr[1];
        float2 p0 = up2(acc[i][0]), p1 = up2(acc[i][1]);
        float2 p2 = up2(acc[i][2]), p3 = up2(acc[i][3]);
        float* dptr = g_hpre + (size_t)d * DD + tx8;
        red_add_v4(dptr,
                   fmaxf(p0.x + x0.x + be0.x, 0.f),
                   fmaxf(p0.y + x0.y + be0.y, 0.f),
                   fmaxf(p1.x + x0.z + be0.z, 0.f),
                   fmaxf(p1.y + x0.w + be0.w, 0.f));
        red_add_v4(dptr + 4,
                   fmaxf(p2.x + x1.x + be1.x, 0.f),
                   fmaxf(p2.y + x1.y + be1.y, 0.f),
                   fmaxf(p3.x + x1.z + be1.z, 0.f),
                   fmaxf(p3.y + x1.w + be1.w, 0.f));
    }
}

// ---------------- 5) GEMM1: y1 = hpre @ W1^T + b1, accumulate BN stats ----------
__global__ __launch_bounds__(256, 2) void k_gemm1(const float* __restrict__ bias) {
    __shared__ float As[128 * 36];
    __shared__ float Bs[32 * 128];
    __shared__ float sSum[128];
    __shared__ float sSq[128];
    int tid = threadIdx.x;
    int m0 = blockIdx.x * 128;
    int n0 = blockIdx.y * 128;
    int tx8 = (tid & 15) * 8;
    int ty8 = (tid >> 4) * 8;
    unsigned long long acc[8][4];
#pragma unroll
    for (int i = 0; i < 8; i++)
#pragma unroll
        for (int j = 0; j < 4; j++) acc[i][j] = 0ull;

    for (int kc = 0; kc < DD; kc += 32) {
#pragma unroll
        for (int r = 0; r < 4; r++) {
            int idx = tid + 256 * r;
            int row = idx >> 3, c4 = idx & 7;
            int m = m0 + row;
            float4 v = make_float4(0.f, 0.f, 0.f, 0.f);
            if (m < NNODE) v = *(const float4*)&g_hpre[(size_t)m * DD + kc + c4 * 4];
            *(float4*)&As[row * 36 + c4 * 4] = v;
        }
#pragma unroll
        for (int r = 0; r < 4; r++) {
            int idx = tid + 256 * r;
            int k = idx >> 5, c4 = idx & 31;
            *(float4*)&Bs[k * 128 + c4 * 4] = *(const float4*)&g_W1T[(size_t)(kc + k) * HH + n0 + c4 * 4];
        }
        __syncthreads();
#pragma unroll
        for (int k = 0; k < 32; k += 4) {
            unsigned long long b[4][4];
#pragma unroll
            for (int kk = 0; kk < 4; kk++) {
                const unsigned long long* bp = (const unsigned long long*)&Bs[(k + kk) * 128 + tx8];
                b[kk][0] = bp[0]; b[kk][1] = bp[1]; b[kk][2] = bp[2]; b[kk][3] = bp[3];
            }
#pragma unroll
            for (int i = 0; i < 8; i++) {
                float4 a4 = *(const float4*)&As[(ty8 + i) * 36 + k];
#pragma unroll
                for (int kk = 0; kk < 4; kk++) {
                    unsigned long long a2 = bcast2(((const float*)&a4)[kk]);
                    ffma2(acc[i][0], a2, b[kk][0]);
                    ffma2(acc[i][1], a2, b[kk][1]);
                    ffma2(acc[i][2], a2, b[kk][2]);
                    ffma2(acc[i][3], a2, b[kk][3]);
                }
            }
        }
        __syncthreads();
    }

    float4 bb0 = *(const float4*)&bias[n0 + tx8];
    float4 bb1 = *(const float4*)&bias[n0 + tx8 + 4];
    float bv[8] = {bb0.x, bb0.y, bb0.z, bb0.w, bb1.x, bb1.y, bb1.z, bb1.w};
    float lsum[8], lsq[8];
#pragma unroll
    for (int j = 0; j < 8; j++) { lsum[j] = 0.f; lsq[j] = 0.f; }
#pragma unroll
    for (int i = 0; i < 8; i++) {
        int m = m0 + ty8 + i;
        if (m < NNODE) {
            float2 pr[4] = {up2(acc[i][0]), up2(acc[i][1]), up2(acc[i][2]), up2(acc[i][3])};
            float v[8];
#pragma unroll
            for (int j = 0; j < 8; j++) {
                float a = (j & 1) ? pr[j >> 1].y : pr[j >> 1].x;
                v[j] = a + bv[j];
                lsum[j] += v[j];
                lsq[j] += v[j] * v[j];
            }
            float4* o = (float4*)&g_y1[(size_t)m * HH + n0 + tx8];
            o[0] = make_float4(v[0], v[1], v[2], v[3]);
            o[1] = make_float4(v[4], v[5], v[6], v[7]);
        }
    }
    if (tid < 128) { sSum[tid] = 0.f; sSq[tid] = 0.f; }
    __syncthreads();
#pragma unroll
    for (int j = 0; j < 8; j++) {
        atomicAdd(&sSum[tx8 + j], lsum[j]);
        atomicAdd(&sSq[tx8 + j], lsq[j]);
    }
    __syncthreads();
    if (tid < 128) {
        atomicAdd(&g_sum1[n0 + tid], sSum[tid]);
        atomicAdd(&g_sq1[n0 + tid], sSq[tid]);
    }
}

// ---------------- 6) fold BN1 stats into scale/shift ----------------------------
__global__ void k_stat1(const float* __restrict__ g, const float* __restrict__ beta) {
    int j = threadIdx.x;
    if (j < HH) {
        float mu = g_sum1[j] / (float)NNODE;
        float var = g_sq1[j] / (float)NNODE - mu * mu;
        float sc = g[j] * rsqrtf(var + BN_EPS);
        g_scale1[j] = sc;
        g_shift1[j] = beta[j] - mu * sc;
    }
}

// ---------------- 7) GEMM2: out = relu(bn1(y1)) @ W2^T + b2, accumulate stats ---
__global__ __launch_bounds__(256, 2) void k_gemm2(const float* __restrict__ bias,
                                                  float* __restrict__ out) {
    __shared__ float As[128 * 36];
    __shared__ float Bs[32 * 128];
    __shared__ float sSum[128];
    __shared__ float sSq[128];
    int tid = threadIdx.x;
    int m0 = blockIdx.x * 128;
    int tx8 = (tid & 15) * 8;
    int ty8 = (tid >> 4) * 8;
    unsigned long long acc[8][4];
#pragma unroll
    for (int i = 0; i < 8; i++)
#pragma unroll
        for (int j = 0; j < 4; j++) acc[i][j] = 0ull;

    for (int kc = 0; kc < HH; kc += 32) {
#pragma unroll
        for (int r = 0; r < 4; r++) {
            int idx = tid + 256 * r;
            int row = idx >> 3, c4 = idx & 7;
            int m = m0 + row;
            int col = kc + c4 * 4;
            float4 v = make_float4(0.f, 0.f, 0.f, 0.f);
            if (m < NNODE) v = *(const float4*)&g_y1[(size_t)m * HH + col];
            float4 sc = *(const float4*)&g_scale1[col];
            float4 sh = *(const float4*)&g_shift1[col];
            v.x = fmaxf(fmaf(v.x, sc.x, sh.x), 0.f);
            v.y = fmaxf(fmaf(v.y, sc.y, sh.y), 0.f);
            v.z = fmaxf(fmaf(v.z, sc.z, sh.z), 0.f);
            v.w = fmaxf(fmaf(v.w, sc.w, sh.w), 0.f);
            *(float4*)&As[row * 36 + c4 * 4] = v;
        }
#pragma unroll
        for (int r = 0; r < 4; r++) {
            int idx = tid + 256 * r;
            int k = idx >> 5, c4 = idx & 31;
            *(float4*)&Bs[k * 128 + c4 * 4] = *(const float4*)&g_W2T[(size_t)(kc + k) * DD + c4 * 4];
        }
        __syncthreads();
#pragma unroll
        for (int k = 0; k < 32; k += 4) {
            unsigned long long b[4][4];
#pragma unroll
            for (int kk = 0; kk < 4; kk++) {
                const unsigned long long* bp = (const unsigned long long*)&Bs[(k + kk) * 128 + tx8];
                b[kk][0] = bp[0]; b[kk][1] = bp[1]; b[kk][2] = bp[2]; b[kk][3] = bp[3];
            }
#pragma unroll
            for (int i = 0; i < 8; i++) {
                float4 a4 = *(const float4*)&As[(ty8 + i) * 36 + k];
#pragma unroll
                for (int kk = 0; kk < 4; kk++) {
                    unsigned long long a2 = bcast2(((const float*)&a4)[kk]);
                    ffma2(acc[i][0], a2, b[kk][0]);
                    ffma2(acc[i][1], a2, b[kk][1]);
                    ffma2(acc[i][2], a2, b[kk][2]);
                    ffma2(acc[i][3], a2, b[kk][3]);
                }
            }
        }
        __syncthreads();
    }

    float4 bb0 = *(const float4*)&bias[tx8];
    float4 bb1 = *(const float4*)&bias[tx8 + 4];
    float bv[8] = {bb0.x, bb0.y, bb0.z, bb0.w, bb1.x, bb1.y, bb1.z, bb1.w};
    float lsum[8], lsq[8];
#pragma unroll
    for (int j = 0; j < 8; j++) { lsum[j] = 0.f; lsq[j] = 0.f; }
#pragma unroll
    for (int i = 0; i < 8; i++) {
        int m = m0 + ty8 + i;
        if (m < NNODE) {
            float2 pr[4] = {up2(acc[i][0]), up2(acc[i][1]), up2(acc[i][2]), up2(acc[i][3])};
            float v[8];
#pragma unroll
            for (int j = 0; j < 8; j++) {
                float a = (j & 1) ? pr[j >> 1].y : pr[j >> 1].x;
                v[j] = a + bv[j];
                lsum[j] += v[j];
                lsq[j] += v[j] * v[j];
            }
            float4* o = (float4*)&out[(size_t)m * DD + tx8];
            o[0] = make_float4(v[0], v[1], v[2], v[3]);
            o[1] = make_float4(v[4], v[5], v[6], v[7]);
        }
    }
    if (tid < 128) { sSum[tid] = 0.f; sSq[tid] = 0.f; }
    __syncthreads();
#pragma unroll
    for (int j = 0; j < 8; j++) {
        atomicAdd(&sSum[tx8 + j], lsum[j]);
        atomicAdd(&sSq[tx8 + j], lsq[j]);
    }
    __syncthreads();
    if (tid < 128) {
        atomicAdd(&g_sum2[tid], sSum[tid]);
        atomicAdd(&g_sq2[tid], sSq[tid]);
    }
}

// ---------------- 8) fold BN2 stats --------------------------------------------
__global__ void k_stat2(const float* __restrict__ g, const float* __restrict__ beta) {
    int j = threadIdx.x;
    if (j < DD) {
        float mu = g_sum2[j] / (float)NNODE;
        float var = g_sq2[j] / (float)NNODE - mu * mu;
        float sc = g[j] * rsqrtf(var + BN_EPS);
        g_scale2[j] = sc;
        g_shift2[j] = beta[j] - mu * sc;
    }
}

// ---------------- 9) final elementwise: out = relu(bn2(out)) --------------------
__global__ void k_final(float* __restrict__ out) {
    int stride = gridDim.x * blockDim.x;
    float4* o4 = (float4*)out;
    for (int i = blockIdx.x * blockDim.x + threadIdx.x; i < NNODE * DD / 4; i += stride) {
        int col = (i & 31) * 4;
        float4 sc = *(const float4*)&g_scale2[col];
        float4 sh = *(const float4*)&g_shift2[col];
        float4 v = o4[i];
        v.x = fmaxf(fmaf(v.x, sc.x, sh.x), 0.f);
        v.y = fmaxf(fmaf(v.y, sc.y, sh.y), 0.f);
        v.z = fmaxf(fmaf(v.z, sc.z, sh.z), 0.f);
        v.w = fmaxf(fmaf(v.w, sc.w, sh.w), 0.f);
        o4[i] = v;
    }
}

// ---------------- launcher ------------------------------------------------------
extern "C" void kernel_launch(void* const* d_in, const int* in_sizes, int n_in,
                              void* d_out, int out_size) {
    const float* x   = (const float*)d_in[0];
    const int*   ei  = (const int*)d_in[1];
    const float* ea  = (const float*)d_in[2];
    const float* We  = (const float*)d_in[3];
    const float* be  = (const float*)d_in[4];
    const float* W1  = (const float*)d_in[5];
    const float* b1  = (const float*)d_in[6];
    const float* g1  = (const float*)d_in[7];
    const float* be1 = (const float*)d_in[8];
    const float* W2  = (const float*)d_in[9];
    const float* b2  = (const float*)d_in[10];
    const float* g2  = (const float*)d_in[11];
    const float* be2 = (const float*)d_in[12];
    const float* eps = (const float*)d_in[13];
    float* out = (float*)d_out;

    cudaFuncSetAttribute(k_edge, cudaFuncAttributeMaxDynamicSharedMemorySize, SM_EDGE_TOTAL);

    k_decode<<<1024, 256>>>(ei);
    k_misc<<<64, 256>>>(We, W1, W2);
    k_hpre<<<2048, 256>>>(x, eps);
    k_edge<<<NEDGE / 128, 256, SM_EDGE_TOTAL>>>(ea, x, be);
    dim3 g1grid((NNODE + 127) / 128, 2);
    k_gemm1<<<g1grid, 256>>>(b1);
    k_stat1<<<1, 256>>>(g1, be1);
    k_gemm2<<<(NNODE + 127) / 128, 256>>>(b2, out);
    k_stat2<<<1, 128>>>(g2, be2);
    k_final<<<2048, 256>>>(out);
}